// round 7
// baseline (speedup 1.0000x reference)
#include <cuda_runtime.h>
#include <cuda_bf16.h>
#include <cstdint>

#define BB   8
#define CIN  256
#define COUT 256
#define HH   128
#define WW   128
#define CK   64                // channels per chunk
#define NCHUNK (CIN/CK)        // 4
#define NT   256               // threads per CTA (8 warps)

// precomputed per-sample pointwise weights, bf16 hi/lo split: [b][o][c]
__device__ __align__(16) __nv_bfloat16 g_whi[BB*COUT*CIN];
__device__ __align__(16) __nv_bfloat16 g_wlo[BB*COUT*CIN];

// ---------------- SMEM layout (bytes) ----------------
static constexpr int S_DWK = 0;                    // 256*9 floats = 9216
static constexpr int S_AHI = 9216;                 // [256 o][64 c] bf16 = 32768 (swizzled)
static constexpr int S_ALO = S_AHI + 32768;        // 32768
static constexpr int S_BHI = S_ALO + 32768;        // [64 c][64 px] bf16 = 8192 (swizzled)
static constexpr int S_BLO = S_BHI + 8192;         // 8192
static constexpr int S_TOTAL = S_BLO + 8192;       // 91136

__device__ __forceinline__ uint32_t smem_u32(const void* p){
    uint32_t a;
    asm("{ .reg .u64 t; cvta.to.shared.u64 t, %1; cvt.u32.u64 %0, t; }" : "=r"(a) : "l"(p));
    return a;
}
__device__ __forceinline__ void cp_async16(uint32_t saddr, const void* g){
    asm volatile("cp.async.ca.shared.global [%0], [%1], 16;" :: "r"(saddr), "l"(g));
}
#define CP_COMMIT() asm volatile("cp.async.commit_group;" ::: "memory")
#define CP_WAIT0()  asm volatile("cp.async.wait_group 0;" ::: "memory")

__device__ __forceinline__ void ldsm_x4(uint32_t* r, uint32_t addr){
    asm volatile("ldmatrix.sync.aligned.m8n8.x4.shared.b16 {%0,%1,%2,%3}, [%4];"
        : "=r"(r[0]), "=r"(r[1]), "=r"(r[2]), "=r"(r[3]) : "r"(addr));
}
__device__ __forceinline__ void ldsm_x4_t(uint32_t* r, uint32_t addr){
    asm volatile("ldmatrix.sync.aligned.m8n8.x4.trans.shared.b16 {%0,%1,%2,%3}, [%4];"
        : "=r"(r[0]), "=r"(r[1]), "=r"(r[2]), "=r"(r[3]) : "r"(addr));
}
__device__ __forceinline__ void mma16816(float* c, const uint32_t* a,
                                         uint32_t b0, uint32_t b1){
    asm volatile("mma.sync.aligned.m16n8k16.row.col.f32.bf16.bf16.f32 "
        "{%0,%1,%2,%3}, {%4,%5,%6,%7}, {%8,%9}, {%0,%1,%2,%3};"
        : "+f"(c[0]), "+f"(c[1]), "+f"(c[2]), "+f"(c[3])
        : "r"(a[0]), "r"(a[1]), "r"(a[2]), "r"(a[3]), "r"(b0), "r"(b1));
}

// ---------------- pre-kernel: build bf16 hi/lo of per-sample weights --------
__global__ void build_w_kernel(const float* __restrict__ delta,
                               const float* __restrict__ pw){
    int i = blockIdx.x * 256 + threadIdx.x;            // [b][o][c]
    if (i >= BB*COUT*CIN) return;
    int c = i & 255, o = (i >> 8) & 255;
    float w = pw[o*CIN + c] + delta[i];
    __nv_bfloat16 hv = __float2bfloat16(w);
    g_whi[i] = hv;
    g_wlo[i] = __float2bfloat16(w - __bfloat162float(hv));
}

// ---------------- fused depthwise 3x3 + per-sample GEMM via mma.sync --------
// grid (HH, 2, BB); 256 threads (8 warps). blockIdx.y = px-half (ph).
// CTA computes out[b, 0:256, h, ph*64 : ph*64+64].
// Warp w: o rows [ (w&3)*64, +64 ), px cols [ ph*64 + (w>>2)*32, +32 ).
__global__ __launch_bounds__(NT, 2)
void fused_mma_kernel(const float* __restrict__ x,
                      const float* __restrict__ dwk,
                      float* __restrict__ out){
    extern __shared__ char smem[];
    const uint32_t sb = smem_u32(smem);
    const int tid = threadIdx.x;
    const int wid = tid >> 5, lid = tid & 31;
    const int h = blockIdx.x, ph = blockIdx.y, b = blockIdx.z;

    for (int i = tid; i < CIN*9; i += NT)
        ((float*)(smem + S_DWK))[i] = dwk[i];

    const int m_base = (wid & 3) * 64;            // o tile of 64
    const int n_base = (wid >> 2) * 32;           // px tile of 32 (within 64)

    float acc[4][4][4];                           // [mt m16][j n8][quad]
    #pragma unroll
    for (int mt = 0; mt < 4; ++mt)
        #pragma unroll
        for (int j = 0; j < 4; ++j)
            #pragma unroll
            for (int q = 0; q < 4; ++q) acc[mt][j][q] = 0.f;

    for (int ch = 0; ch < NCHUNK; ++ch){
        __syncthreads();   // previous chunk's ldmatrix readers done

        // ---- stage A: full-M weights hi/lo -> SMEM via cp.async
        {
            const uint4* ghi = (const uint4*)g_whi;
            const uint4* glo = (const uint4*)g_wlo;
            #pragma unroll
            for (int it = 0; it < 8; ++it){
                int i   = tid + it*NT;                // 0..2047
                int o   = i >> 3, ck16 = i & 7;       // 8 x 16B per o-row
                uint32_t byte = (uint32_t)(o*128 + ck16*16);
                uint32_t sw   = byte ^ ((uint32_t)(o & 7) << 4);
                int gi = (b*COUT + o)*32 + ch*8 + ck16;
                cp_async16(sb + S_AHI + sw, ghi + gi);
                cp_async16(sb + S_ALO + sw, glo + gi);
            }
            CP_COMMIT();
        }

        // ---- stage B: depthwise 3x3 (64 px of this half) -> bf16 split -> SMEM
        #pragma unroll
        for (int it = 0; it < 8; ++it){
            int cl = wid + it*8;                      // 0..63
            int c  = ch*CK + cl;
            const float* kk = (const float*)(smem + S_DWK) + c*9;
            float s0 = 0.f, s1 = 0.f;
            const float* xch = x + (size_t)((b*CIN + c)*HH)*WW;
            const int px0 = ph*64 + lid*2;
            #pragma unroll
            for (int r = 0; r < 3; ++r){
                int hh2 = h - 1 + r;
                float2 f = make_float2(0.f, 0.f);
                float lfE = 0.f, rtE = 0.f;
                if (hh2 >= 0 && hh2 < HH){
                    const float* xr = xch + (size_t)hh2*WW;
                    f = *(const float2*)(xr + px0);
                    if (lid == 0  && ph == 1) lfE = xr[63];
                    if (lid == 31 && ph == 0) rtE = xr[64];
                }
                float lf = __shfl_up_sync(0xffffffffu, f.y, 1);
                float rt = __shfl_down_sync(0xffffffffu, f.x, 1);
                if (lid == 0)  lf = lfE;
                if (lid == 31) rt = rtE;
                float ka = kk[r*3+0], kb = kk[r*3+1], kc = kk[r*3+2];
                s0 += ka*lf  + kb*f.x + kc*f.y;
                s1 += ka*f.x + kb*f.y + kc*rt;
            }
            __nv_bfloat16 h0 = __float2bfloat16(s0), h1 = __float2bfloat16(s1);
            __nv_bfloat16 l0 = __float2bfloat16(s0 - __bfloat162float(h0));
            __nv_bfloat16 l1 = __float2bfloat16(s1 - __bfloat162float(h1));
            __nv_bfloat162 hp; hp.x = h0; hp.y = h1;
            __nv_bfloat162 lp; lp.x = l0; lp.y = l1;
            uint32_t byte = (uint32_t)(cl*128 + lid*4);
            uint32_t sw   = byte ^ ((uint32_t)(cl & 7) << 4);
            *(uint32_t*)(smem + S_BHI + sw) = *(uint32_t*)&hp;
            *(uint32_t*)(smem + S_BLO + sw) = *(uint32_t*)&lp;
        }
        CP_WAIT0();
        __syncthreads();

        // ---- mma: term order lo*hi -> hi*hi (reuse B) -> hi*lo (reuse A)
        #pragma unroll
        for (int ks = 0; ks < 4; ++ks){
            uint32_t ar[4][4], br[2][4];
            const uint32_t acol = ((uint32_t)(ks*32 + (lid >> 4)*16));
            // A_lo frags
            #pragma unroll
            for (int mt = 0; mt < 4; ++mt){
                int row = m_base + mt*16 + (lid & 15);
                ldsm_x4(ar[mt], sb + S_ALO + (uint32_t)row*128
                                + (acol ^ ((uint32_t)(row & 7) << 4)));
            }
            // B_hi frags — full within-row offset goes through the swizzle XOR
            #pragma unroll
            for (int nt = 0; nt < 2; ++nt){
                int krow = ks*16 + (lid & 15);
                uint32_t col = ((uint32_t)(n_base*2 + nt*32 + (lid >> 4)*16))
                               ^ ((uint32_t)(krow & 7) << 4);
                ldsm_x4_t(br[nt], sb + S_BHI + (uint32_t)krow*128 + col);
            }
            #pragma unroll
            for (int mt = 0; mt < 4; ++mt)
                #pragma unroll
                for (int j = 0; j < 4; ++j)
                    mma16816(acc[mt][j], ar[mt],
                             br[j>>1][(j&1)*2], br[j>>1][(j&1)*2 + 1]);
            // A_hi frags (B reused)
            #pragma unroll
            for (int mt = 0; mt < 4; ++mt){
                int row = m_base + mt*16 + (lid & 15);
                ldsm_x4(ar[mt], sb + S_AHI + (uint32_t)row*128
                                + (acol ^ ((uint32_t)(row & 7) << 4)));
            }
            #pragma unroll
            for (int mt = 0; mt < 4; ++mt)
                #pragma unroll
                for (int j = 0; j < 4; ++j)
                    mma16816(acc[mt][j], ar[mt],
                             br[j>>1][(j&1)*2], br[j>>1][(j&1)*2 + 1]);
            // B_lo frags (A_hi reused)
            #pragma unroll
            for (int nt = 0; nt < 2; ++nt){
                int krow = ks*16 + (lid & 15);
                uint32_t col = ((uint32_t)(n_base*2 + nt*32 + (lid >> 4)*16))
                               ^ ((uint32_t)(krow & 7) << 4);
                ldsm_x4_t(br[nt], sb + S_BLO + (uint32_t)krow*128 + col);
            }
            #pragma unroll
            for (int mt = 0; mt < 4; ++mt)
                #pragma unroll
                for (int j = 0; j < 4; ++j)
                    mma16816(acc[mt][j], ar[mt],
                             br[j>>1][(j&1)*2], br[j>>1][(j&1)*2 + 1]);
        }
    }

    // ---- epilogue: register accumulators -> gmem (float2 stores)
    // C fragment: c0,c1 at (o, px), c2,c3 at (o+8, px). One o step = HH*WW floats.
    #pragma unroll
    for (int mt = 0; mt < 4; ++mt){
        #pragma unroll
        for (int j = 0; j < 4; ++j){
            int o  = m_base + mt*16 + (lid >> 2);
            int px = ph*64 + n_base + j*8 + (lid & 3)*2;
            float* p = out + ((size_t)(b*COUT + o)*HH + h)*WW + px;
            *(float2*)p = make_float2(acc[mt][j][0], acc[mt][j][1]);
            *(float2*)(p + (size_t)8*HH*WW) = make_float2(acc[mt][j][2], acc[mt][j][3]);
        }
    }
}

// ---------------------------------------------------------------------------
extern "C" void kernel_launch(void* const* d_in, const int* in_sizes, int n_in,
                              void* d_out, int out_size){
    const float* x     = (const float*)d_in[0];
    const float* delta = (const float*)d_in[1];
    const float* dwk   = (const float*)d_in[2];
    const float* pw    = (const float*)d_in[3];
    float* out = (float*)d_out;

    cudaFuncSetAttribute(fused_mma_kernel,
                         cudaFuncAttributeMaxDynamicSharedMemorySize, S_TOTAL);

    build_w_kernel<<<(BB*COUT*CIN + 255)/256, 256>>>(delta, pw);
    fused_mma_kernel<<<dim3(HH, 2, BB), NT, S_TOTAL>>>(x, dwk, out);
}

// round 8
// speedup vs baseline: 1.5562x; 1.5562x over previous
#include <cuda_runtime.h>
#include <cuda_bf16.h>
#include <cstdint>

#define BB   8
#define CIN  256
#define COUT 256
#define HH   128
#define WW   128
#define CK   64                // channels per chunk
#define NCHUNK (CIN/CK)        // 4
#define NT   256               // threads per CTA (8 warps)

// precomputed per-sample pointwise weights, bf16 hi/lo split: [b][o][c]
__device__ __align__(16) __nv_bfloat16 g_whi[BB*COUT*CIN];
__device__ __align__(16) __nv_bfloat16 g_wlo[BB*COUT*CIN];

// ---------------- SMEM layout (byte offsets) ----------------
static constexpr int S_DWK  = 0;                   // 256*9 floats = 9216
static constexpr int S_AHI  = 9216;                // [128 o][64 c] bf16 = 16384 (swizzled)
static constexpr int S_ALO  = S_AHI + 16384;       // 16384
static constexpr int S_B0HI = S_ALO + 16384;       // [64 c][128 px] bf16 = 16384 (swizzled)
static constexpr int S_B0LO = S_B0HI + 16384;
static constexpr int S_B1HI = S_B0LO + 16384;
static constexpr int S_B1LO = S_B1HI + 16384;
static constexpr int S_TOTAL = S_B1LO + 16384;     // 107520

__device__ __forceinline__ uint32_t smem_u32(const void* p){
    uint32_t a;
    asm("{ .reg .u64 t; cvta.to.shared.u64 t, %1; cvt.u32.u64 %0, t; }" : "=r"(a) : "l"(p));
    return a;
}
__device__ __forceinline__ void cp_async16(uint32_t saddr, const void* g){
    asm volatile("cp.async.ca.shared.global [%0], [%1], 16;" :: "r"(saddr), "l"(g));
}
#define CP_COMMIT() asm volatile("cp.async.commit_group;" ::: "memory")
#define CP_WAIT0()  asm volatile("cp.async.wait_group 0;" ::: "memory")

__device__ __forceinline__ void ldsm_x4(uint32_t* r, uint32_t addr){
    asm volatile("ldmatrix.sync.aligned.m8n8.x4.shared.b16 {%0,%1,%2,%3}, [%4];"
        : "=r"(r[0]), "=r"(r[1]), "=r"(r[2]), "=r"(r[3]) : "r"(addr));
}
__device__ __forceinline__ void ldsm_x4_t(uint32_t* r, uint32_t addr){
    asm volatile("ldmatrix.sync.aligned.m8n8.x4.trans.shared.b16 {%0,%1,%2,%3}, [%4];"
        : "=r"(r[0]), "=r"(r[1]), "=r"(r[2]), "=r"(r[3]) : "r"(addr));
}
__device__ __forceinline__ void mma16816(float* c, const uint32_t* a,
                                         uint32_t b0, uint32_t b1){
    asm volatile("mma.sync.aligned.m16n8k16.row.col.f32.bf16.bf16.f32 "
        "{%0,%1,%2,%3}, {%4,%5,%6,%7}, {%8,%9}, {%0,%1,%2,%3};"
        : "+f"(c[0]), "+f"(c[1]), "+f"(c[2]), "+f"(c[3])
        : "r"(a[0]), "r"(a[1]), "r"(a[2]), "r"(a[3]), "r"(b0), "r"(b1));
}

// ---------------- pre-kernel: build bf16 hi/lo of per-sample weights --------
__global__ void build_w_kernel(const float* __restrict__ delta,
                               const float* __restrict__ pw){
    int i = blockIdx.x * 256 + threadIdx.x;            // [b][o][c]
    if (i >= BB*COUT*CIN) return;
    int c = i & 255, o = (i >> 8) & 255;
    float w = pw[o*CIN + c] + delta[i];
    __nv_bfloat16 hv = __float2bfloat16(w);
    g_whi[i] = hv;
    g_wlo[i] = __float2bfloat16(w - __bfloat162float(hv));
}

// ---------------- fused depthwise 3x3 + per-sample GEMM via mma.sync --------
// grid (HH, 2, BB); 256 threads (8 warps). blockIdx.y = o-half.
// CTA computes out[b, half*128 : half*128+128, h, 0:128].
// Warp w: o rows [ (w&3)*32, +32 ), px cols [ (w>>2)*64, +64 ).
// Software pipeline: depthwise of chunk ch+1 interleaved with mma of chunk ch
// (double-buffered B); A single-buffered, reloaded between chunks via cp.async.
__global__ __launch_bounds__(NT, 2)
void fused_mma_kernel(const float* __restrict__ x,
                      const float* __restrict__ dwk,
                      float* __restrict__ out){
    extern __shared__ char smem[];
    const uint32_t sb = smem_u32(smem);
    const int tid = threadIdx.x;
    const int wid = tid >> 5, lid = tid & 31;
    const int h = blockIdx.x, half = blockIdx.y, b = blockIdx.z;

    for (int i = tid; i < CIN*9; i += NT)
        ((float*)(smem + S_DWK))[i] = dwk[i];

    const int m_base = (wid & 3) * 32;
    const int n_base = (wid >> 2) * 64;
    const uint32_t lmask = (uint32_t)(lid & 7) << 4;   // swizzle xor for this lane

    // ---- depthwise one channel-iteration of `chunk`, store to B buffer
    auto dw_iter = [&](int chunk, int it, int dstHI){
        int cl = wid + it*8;                      // 0..63
        int c  = chunk*CK + cl;
        const float* kk = (const float*)(smem + S_DWK) + c*9;
        float s0=0.f, s1=0.f, s2=0.f, s3=0.f;
        const float* xrow = x + (size_t)((b*CIN + c)*HH)*WW + lid*4;
        #pragma unroll
        for (int r = 0; r < 3; ++r){
            int hh2 = h - 1 + r;
            float4 f = make_float4(0.f,0.f,0.f,0.f);
            if (hh2 >= 0 && hh2 < HH) f = *(const float4*)(xrow + hh2*WW);
            float lf = __shfl_up_sync(0xffffffffu, f.w, 1);
            float rt = __shfl_down_sync(0xffffffffu, f.x, 1);
            if (lid == 0)  lf = 0.f;
            if (lid == 31) rt = 0.f;
            float ka = kk[r*3+0], kb = kk[r*3+1], kc = kk[r*3+2];
            s0 += ka*lf  + kb*f.x + kc*f.y;
            s1 += ka*f.x + kb*f.y + kc*f.z;
            s2 += ka*f.y + kb*f.z + kc*f.w;
            s3 += ka*f.z + kb*f.w + kc*rt;
        }
        __nv_bfloat16 h0 = __float2bfloat16(s0), h1 = __float2bfloat16(s1);
        __nv_bfloat16 h2 = __float2bfloat16(s2), h3 = __float2bfloat16(s3);
        __nv_bfloat16 l0 = __float2bfloat16(s0 - __bfloat162float(h0));
        __nv_bfloat16 l1 = __float2bfloat16(s1 - __bfloat162float(h1));
        __nv_bfloat16 l2 = __float2bfloat16(s2 - __bfloat162float(h2));
        __nv_bfloat16 l3 = __float2bfloat16(s3 - __bfloat162float(h3));
        __nv_bfloat162 hp0; hp0.x = h0; hp0.y = h1;
        __nv_bfloat162 hp1; hp1.x = h2; hp1.y = h3;
        __nv_bfloat162 lp0; lp0.x = l0; lp0.y = l1;
        __nv_bfloat162 lp1; lp1.x = l2; lp1.y = l3;
        uint32_t byte = (uint32_t)(cl*256 + lid*8);
        uint32_t sw   = byte ^ ((uint32_t)(cl & 7) << 4);
        *(uint2*)(smem + dstHI + sw)         = make_uint2(*(uint32_t*)&hp0, *(uint32_t*)&hp1);
        *(uint2*)(smem + dstHI + 16384 + sw) = make_uint2(*(uint32_t*)&lp0, *(uint32_t*)&lp1);
    };

    // ---- cp.async of A-tile (hi/lo) for `chunk`
    auto load_A = [&](int chunk){
        const uint4* ghi = (const uint4*)g_whi;
        const uint4* glo = (const uint4*)g_wlo;
        #pragma unroll
        for (int it = 0; it < 4; ++it){
            int i   = tid + it*NT;                // 0..1023
            int o   = i >> 3, ck16 = i & 7;       // 8 x 16B per o-row
            uint32_t byte = (uint32_t)(o*128 + ck16*16);
            uint32_t sw   = byte ^ ((uint32_t)(o & 7) << 4);
            int gi = (b*COUT + half*128 + o)*32 + chunk*8 + ck16;
            cp_async16(sb + S_AHI + sw, ghi + gi);
            cp_async16(sb + S_ALO + sw, glo + gi);
        }
        CP_COMMIT();
    };

    float acc[2][8][4];
    #pragma unroll
    for (int mt = 0; mt < 2; ++mt)
        #pragma unroll
        for (int j = 0; j < 8; ++j)
            #pragma unroll
            for (int q = 0; q < 4; ++q) acc[mt][j][q] = 0.f;

    // ---- prologue: A[0] + depthwise[0] -> B0
    load_A(0);
    #pragma unroll
    for (int it = 0; it < 8; ++it) dw_iter(0, it, S_B0HI);
    CP_WAIT0();
    __syncthreads();

    for (int ch = 0; ch < NCHUNK; ++ch){
        const int curHI  = (ch & 1) ? S_B1HI : S_B0HI;
        const int nextHI = (ch & 1) ? S_B0HI : S_B1HI;
        const bool hasNext = (ch < NCHUNK - 1);

        // ---- interleaved region: dw[ch+1] between the mma ks-blocks of ch
        #pragma unroll
        for (int ks = 0; ks < 4; ++ks){
            if (hasNext){
                dw_iter(ch+1, 2*ks,     nextHI);
                dw_iter(ch+1, 2*ks + 1, nextHI);
            }
            uint32_t ar[2][4];
            uint32_t br[4][4];
            #pragma unroll
            for (int term = 0; term < 3; ++term){
                const uint32_t abase = sb + ((term == 1) ? S_ALO : S_AHI);
                #pragma unroll
                for (int mt = 0; mt < 2; ++mt){
                    int row = m_base + mt*16 + (lid & 15);
                    uint32_t col = ((uint32_t)(ks*32 + (lid >> 4)*16)) ^ lmask;
                    ldsm_x4(ar[mt], abase + (uint32_t)row*128 + col);
                }
                if (term != 1){   // term 1 reuses term 0's B (both BHI)
                    const uint32_t bbase = sb + ((term == 2) ? curHI + 16384 : curHI);
                    #pragma unroll
                    for (int nt = 0; nt < 4; ++nt){
                        int krow = ks*16 + (lid & 15);
                        uint32_t col = ((uint32_t)(nt*32 + (lid >> 4)*16)) ^ lmask;
                        ldsm_x4_t(br[nt], bbase + (uint32_t)krow*256
                                          + (uint32_t)(n_base*2) + col);
                    }
                }
                #pragma unroll
                for (int mt = 0; mt < 2; ++mt)
                    #pragma unroll
                    for (int j = 0; j < 8; ++j)
                        mma16816(acc[mt][j], ar[mt],
                                 br[j>>1][(j&1)*2], br[j>>1][(j&1)*2 + 1]);
            }
        }
        __syncthreads();   // mma[ch] readers done (A + B[cur]); dw[ch+1] stores done

        if (hasNext){
            load_A(ch+1);  // safe: all A readers passed the barrier
            CP_WAIT0();
        }
        __syncthreads();   // A[ch+1] visible to all warps
    }

    // ---- epilogue: register accumulators -> gmem (float2 stores)
    // C fragment: c0,c1 at (o, px), c2,c3 at (o+8, px). One o step = HH*WW floats.
    #pragma unroll
    for (int mt = 0; mt < 2; ++mt){
        #pragma unroll
        for (int j = 0; j < 8; ++j){
            int o  = half*128 + m_base + mt*16 + (lid >> 2);
            int px = n_base + j*8 + (lid & 3)*2;
            float* p = out + ((size_t)(b*COUT + o)*HH + h)*WW + px;
            *(float2*)p = make_float2(acc[mt][j][0], acc[mt][j][1]);
            *(float2*)(p + (size_t)8*HH*WW) = make_float2(acc[mt][j][2], acc[mt][j][3]);
        }
    }
}

// ---------------------------------------------------------------------------
extern "C" void kernel_launch(void* const* d_in, const int* in_sizes, int n_in,
                              void* d_out, int out_size){
    const float* x     = (const float*)d_in[0];
    const float* delta = (const float*)d_in[1];
    const float* dwk   = (const float*)d_in[2];
    const float* pw    = (const float*)d_in[3];
    float* out = (float*)d_out;

    cudaFuncSetAttribute(fused_mma_kernel,
                         cudaFuncAttributeMaxDynamicSharedMemorySize, S_TOTAL);

    build_w_kernel<<<(BB*COUT*CIN + 255)/256, 256>>>(delta, pw);
    fused_mma_kernel<<<dim3(HH, 2, BB), NT, S_TOTAL>>>(x, dwk, out);
}

// round 9
// speedup vs baseline: 1.9900x; 1.2787x over previous
#include <cuda_runtime.h>
#include <cuda_fp16.h>
#include <cstdint>

#define BB   8
#define CIN  256
#define COUT 256
#define HH   128
#define WW   128
#define CK   64                // channels per chunk
#define NCHUNK (CIN/CK)        // 4
#define NT   256               // threads per CTA (8 warps)

// precomputed per-sample pointwise weights, fp16 hi/lo split: [b][o][c]
__device__ __align__(16) __half g_whi[BB*COUT*CIN];
__device__ __align__(16) __half g_wlo[BB*COUT*CIN];

// ---------------- SMEM layout (bytes) ----------------
static constexpr int S_DWK = 0;                    // 256*9 floats = 9216
static constexpr int S_AHI = 9216;                 // [128 o][64 c] fp16 = 16384 (swizzled)
static constexpr int S_ALO = S_AHI + 16384;        // 16384
static constexpr int S_B   = S_ALO + 16384;        // [64 c][128 px] fp16 = 16384 (swizzled)
static constexpr int S_TOTAL = S_B + 16384;        // 58368

__device__ __forceinline__ uint32_t smem_u32(const void* p){
    uint32_t a;
    asm("{ .reg .u64 t; cvta.to.shared.u64 t, %1; cvt.u32.u64 %0, t; }" : "=r"(a) : "l"(p));
    return a;
}
__device__ __forceinline__ void cp_async16(uint32_t saddr, const void* g){
    asm volatile("cp.async.ca.shared.global [%0], [%1], 16;" :: "r"(saddr), "l"(g));
}
#define CP_COMMIT() asm volatile("cp.async.commit_group;" ::: "memory")
#define CP_WAIT0()  asm volatile("cp.async.wait_group 0;" ::: "memory")

__device__ __forceinline__ void ldsm_x4(uint32_t* r, uint32_t addr){
    asm volatile("ldmatrix.sync.aligned.m8n8.x4.shared.b16 {%0,%1,%2,%3}, [%4];"
        : "=r"(r[0]), "=r"(r[1]), "=r"(r[2]), "=r"(r[3]) : "r"(addr));
}
__device__ __forceinline__ void ldsm_x4_t(uint32_t* r, uint32_t addr){
    asm volatile("ldmatrix.sync.aligned.m8n8.x4.trans.shared.b16 {%0,%1,%2,%3}, [%4];"
        : "=r"(r[0]), "=r"(r[1]), "=r"(r[2]), "=r"(r[3]) : "r"(addr));
}
__device__ __forceinline__ void mma16816(float* c, const uint32_t* a,
                                         uint32_t b0, uint32_t b1){
    asm volatile("mma.sync.aligned.m16n8k16.row.col.f32.f16.f16.f32 "
        "{%0,%1,%2,%3}, {%4,%5,%6,%7}, {%8,%9}, {%0,%1,%2,%3};"
        : "+f"(c[0]), "+f"(c[1]), "+f"(c[2]), "+f"(c[3])
        : "r"(a[0]), "r"(a[1]), "r"(a[2]), "r"(a[3]), "r"(b0), "r"(b1));
}

// ---------------- pre-kernel: build fp16 hi/lo of per-sample weights --------
__global__ void build_w_kernel(const float* __restrict__ delta,
                               const float* __restrict__ pw){
    int i = blockIdx.x * 256 + threadIdx.x;            // [b][o][c]
    if (i >= BB*COUT*CIN) return;
    int c = i & 255, o = (i >> 8) & 255;
    float w = pw[o*CIN + c] + delta[i];
    __half hv = __float2half_rn(w);
    g_whi[i] = hv;
    g_wlo[i] = __float2half_rn(w - __half2float(hv));
}

// ---------------- fused depthwise 3x3 + per-sample GEMM via mma.sync --------
// grid (HH, 2, BB); 256 threads (8 warps). blockIdx.y = o-half.
// CTA computes out[b, half*128 : half*128+128, h, 0:128].
// Warp w: o rows [ (w&3)*32, +32 ), px cols [ (w>>2)*64, +64 ).
__global__ __launch_bounds__(NT, 2)
void fused_mma_kernel(const float* __restrict__ x,
                      const float* __restrict__ dwk,
                      float* __restrict__ out){
    extern __shared__ char smem[];
    const uint32_t sb = smem_u32(smem);
    const int tid = threadIdx.x;
    const int wid = tid >> 5, lid = tid & 31;
    const int h = blockIdx.x, half = blockIdx.y, b = blockIdx.z;

    for (int i = tid; i < CIN*9; i += NT)
        ((float*)(smem + S_DWK))[i] = dwk[i];

    const int m_base = (wid & 3) * 32;
    const int n_base = (wid >> 2) * 64;
    const uint32_t lmask = (uint32_t)(lid & 7) << 4;   // swizzle xor for this lane

    float acc[2][8][4];
    #pragma unroll
    for (int mt = 0; mt < 2; ++mt)
        #pragma unroll
        for (int j = 0; j < 8; ++j)
            #pragma unroll
            for (int q = 0; q < 4; ++q) acc[mt][j][q] = 0.f;

    for (int ch = 0; ch < NCHUNK; ++ch){
        __syncthreads();   // previous chunk's ldmatrix readers done

        // ---- stage A: weights hi/lo -> SMEM via cp.async (overlaps depthwise)
        {
            const uint4* ghi = (const uint4*)g_whi;
            const uint4* glo = (const uint4*)g_wlo;
            #pragma unroll
            for (int it = 0; it < 4; ++it){
                int i   = tid + it*NT;                // 0..1023
                int o   = i >> 3, ck16 = i & 7;       // 8 x 16B per o-row
                uint32_t byte = (uint32_t)(o*128 + ck16*16);
                uint32_t sw   = byte ^ ((uint32_t)(o & 7) << 4);
                int gi = (b*COUT + half*128 + o)*32 + ch*8 + ck16;
                cp_async16(sb + S_AHI + sw, ghi + gi);
                cp_async16(sb + S_ALO + sw, glo + gi);
            }
            CP_COMMIT();
        }

        // ---- stage B: depthwise 3x3 -> fp16 -> SMEM [c][px] swizzled
        #pragma unroll
        for (int it = 0; it < 8; ++it){
            int cl = wid + it*8;                      // 0..63
            int c  = ch*CK + cl;
            const float* kk = (const float*)(smem + S_DWK) + c*9;
            float s0=0.f, s1=0.f, s2=0.f, s3=0.f;
            const float* xrow = x + (size_t)((b*CIN + c)*HH)*WW + lid*4;
            #pragma unroll
            for (int r = 0; r < 3; ++r){
                int hh2 = h - 1 + r;
                float4 f = make_float4(0.f,0.f,0.f,0.f);
                if (hh2 >= 0 && hh2 < HH) f = *(const float4*)(xrow + hh2*WW);
                float lf = __shfl_up_sync(0xffffffffu, f.w, 1);
                float rt = __shfl_down_sync(0xffffffffu, f.x, 1);
                if (lid == 0)  lf = 0.f;
                if (lid == 31) rt = 0.f;
                float ka = kk[r*3+0], kb = kk[r*3+1], kc = kk[r*3+2];
                s0 += ka*lf  + kb*f.x + kc*f.y;
                s1 += ka*f.x + kb*f.y + kc*f.z;
                s2 += ka*f.y + kb*f.z + kc*f.w;
                s3 += ka*f.z + kb*f.w + kc*rt;
            }
            __half2 p0 = __floats2half2_rn(s0, s1);
            __half2 p1 = __floats2half2_rn(s2, s3);
            uint32_t byte = (uint32_t)(cl*256 + lid*8);
            uint32_t sw   = byte ^ ((uint32_t)(cl & 7) << 4);
            *(uint2*)(smem + S_B + sw) = make_uint2(*(uint32_t*)&p0, *(uint32_t*)&p1);
        }
        CP_WAIT0();
        __syncthreads();

        // ---- mma: 2 terms (A_hi*B, A_lo*B), B fragments loaded once per ks
        #pragma unroll
        for (int ks = 0; ks < 4; ++ks){
            uint32_t ar[2][4];
            uint32_t br[4][4];
            // B frags (shared by both terms)
            #pragma unroll
            for (int nt = 0; nt < 4; ++nt){
                int krow = ks*16 + (lid & 15);
                uint32_t col = ((uint32_t)(nt*32 + (lid >> 4)*16)) ^ lmask;
                ldsm_x4_t(br[nt], sb + S_B + (uint32_t)krow*256
                                  + (uint32_t)(n_base*2) + col);
            }
            #pragma unroll
            for (int term = 0; term < 2; ++term){
                const uint32_t abase = sb + ((term == 1) ? S_ALO : S_AHI);
                #pragma unroll
                for (int mt = 0; mt < 2; ++mt){
                    int row = m_base + mt*16 + (lid & 15);
                    uint32_t col = ((uint32_t)(ks*32 + (lid >> 4)*16)) ^ lmask;
                    ldsm_x4(ar[mt], abase + (uint32_t)row*128 + col);
                }
                #pragma unroll
                for (int mt = 0; mt < 2; ++mt)
                    #pragma unroll
                    for (int j = 0; j < 8; ++j)
                        mma16816(acc[mt][j], ar[mt],
                                 br[j>>1][(j&1)*2], br[j>>1][(j&1)*2 + 1]);
            }
        }
    }

    // ---- epilogue: register accumulators -> gmem (float2 stores)
    // C fragment: c0,c1 at (o, px), c2,c3 at (o+8, px). One o step = HH*WW floats.
    #pragma unroll
    for (int mt = 0; mt < 2; ++mt){
        #pragma unroll
        for (int j = 0; j < 8; ++j){
            int o  = half*128 + m_base + mt*16 + (lid >> 2);
            int px = n_base + j*8 + (lid & 3)*2;
            float* p = out + ((size_t)(b*COUT + o)*HH + h)*WW + px;
            *(float2*)p = make_float2(acc[mt][j][0], acc[mt][j][1]);
            *(float2*)(p + (size_t)8*HH*WW) = make_float2(acc[mt][j][2], acc[mt][j][3]);
        }
    }
}

// ---------------------------------------------------------------------------
extern "C" void kernel_launch(void* const* d_in, const int* in_sizes, int n_in,
                              void* d_out, int out_size){
    const float* x     = (const float*)d_in[0];
    const float* delta = (const float*)d_in[1];
    const float* dwk   = (const float*)d_in[2];
    const float* pw    = (const float*)d_in[3];
    float* out = (float*)d_out;

    cudaFuncSetAttribute(fused_mma_kernel,
                         cudaFuncAttributeMaxDynamicSharedMemorySize, S_TOTAL);

    build_w_kernel<<<(BB*COUT*CIN + 255)/256, 256>>>(delta, pw);
    fused_mma_kernel<<<dim3(HH, 2, BB), NT, S_TOTAL>>>(x, dwk, out);
}